// round 6
// baseline (speedup 1.0000x reference)
#include <cuda_runtime.h>

#define BB 256
#define NN 512
#define INF 10
#define HIDF 32
#define ROWS_PW 4                    // rows per warp (shared s loads)
#define WARPS 8
#define THREADS (WARPS * 32)
#define ROWS_PB (WARPS * ROWS_PW)    // 32 rows per block
#define CHUNKS (NN / ROWS_PB)        // 16

typedef unsigned long long u64;

// ---- packed f32x2 helpers (sm_103a FFMA2 path, PTX-only) -------------------
__device__ __forceinline__ u64 pk2(float lo, float hi) {
    u64 r; asm("mov.b64 %0,{%1,%2};" : "=l"(r) : "f"(lo), "f"(hi)); return r;
}
__device__ __forceinline__ void upk2(u64 v, float& lo, float& hi) {
    asm("mov.b64 {%0,%1},%2;" : "=f"(lo), "=f"(hi) : "l"(v));
}
__device__ __forceinline__ u64 fma2(u64 a, u64 b, u64 c) {
    u64 r; asm("fma.rn.f32x2 %0,%1,%2,%3;" : "=l"(r) : "l"(a), "l"(b), "l"(c)); return r;
}
__device__ __forceinline__ u64 mul2f(u64 a, u64 b) {
    u64 r; asm("mul.rn.f32x2 %0,%1,%2;" : "=l"(r) : "l"(a), "l"(b)); return r;
}
__device__ __forceinline__ u64 add2f(u64 a, u64 b) {
    u64 r; asm("add.rn.f32x2 %0,%1,%2;" : "=l"(r) : "l"(a), "l"(b)); return r;
}

// ---------------------------------------------------------------------------
// Fused kernel, u-outer structure with deferred normalization.
//   Phase 1: s[b] transposed into smem + M = Q K^T
//   Phase 2: t = s.M for the block's 32 rows
//   Phase 3: warp owns 4 rows (2 f32x2 pairs). For each column group u:
//            10 shared LDS serve all 4 rows; raw v = (t.s)^2 * G is stored
//            to out immediately; packed row-sums accumulate in 2 regs.
//   Phase 4: warp-reduce sums; epilogue rescales own raw stores in place
//            (same-thread RAW through L2 — no fence needed).
// ---------------------------------------------------------------------------
__global__ __launch_bounds__(THREADS, 3) void attn_fused(
    const float* __restrict__ s,
    const float* __restrict__ Gmat,
    const float* __restrict__ Qw,
    const float* __restrict__ Kw,
    float* __restrict__ out) {
    __shared__ float s_sm[INF][NN];      // s[b] transposed: s_sm[i][n]
    __shared__ float M_sm[INF][INF];     // Q @ K^T
    __shared__ float t_sm[ROWS_PB][INF]; // t rows for this chunk

    const int tid = threadIdx.x;
    const int b = blockIdx.x / CHUNKS;
    const int row0 = (blockIdx.x % CHUNKS) * ROWS_PB;

    // ---- Phase 1a: s[b] -> smem transposed (STS conflict-free per i)
    const float* sb = s + (size_t)b * NN * INF;
    for (int n = tid; n < NN; n += THREADS) {
#pragma unroll
        for (int i = 0; i < INF; i++)
            s_sm[i][n] = sb[n * INF + i];
    }
    // ---- Phase 1b: M[a][p] = sum_m Qw[a][m]*Kw[p][m]
    if (tid < INF * INF) {
        const int a = tid / INF, p = tid % INF;
        float acc = 0.0f;
#pragma unroll
        for (int m = 0; m < HIDF; m++)
            acc = fmaf(Qw[a * HIDF + m], Kw[p * HIDF + m], acc);
        M_sm[a][p] = acc;
    }
    __syncthreads();

    // ---- Phase 2: t_sm[r][o] = sum_l s_sm[l][row0+r] * M[l][o]
    if (tid < ROWS_PB) {
        const int n = row0 + tid;
        float sv[INF];
#pragma unroll
        for (int l = 0; l < INF; l++) sv[l] = s_sm[l][n];
#pragma unroll
        for (int o = 0; o < INF; o++) {
            float acc = 0.0f;
#pragma unroll
            for (int l = 0; l < INF; l++) acc = fmaf(sv[l], M_sm[l][o], acc);
            t_sm[tid][o] = acc;
        }
    }
    __syncthreads();

    // ---- Phase 3: main loop (warp-private 4 rows)
    const int warp = tid >> 5;
    const int lane = tid & 31;
    const int r0 = warp * ROWS_PW;

    u64 tp0[INF], tp1[INF];
#pragma unroll
    for (int i = 0; i < INF; i++) {
        tp0[i] = pk2(t_sm[r0 + 0][i], t_sm[r0 + 1][i]);
        tp1[i] = pk2(t_sm[r0 + 2][i], t_sm[r0 + 3][i]);
    }

    const float* gb = Gmat + ((size_t)b * NN + row0 + r0) * NN;
    float* ob = out + ((size_t)b * NN + row0 + r0) * NN;

    u64 sumA = pk2(0.0f, 0.0f);
    u64 sumB = pk2(0.0f, 0.0f);

#pragma unroll
    for (int u = 0; u < 16; u++) {
        const int j = lane + (u << 5);
        u64 d0 = pk2(0.0f, 0.0f);
        u64 d1 = pk2(0.0f, 0.0f);
#pragma unroll
        for (int i = 0; i < INF; i++) {
            const float sj = s_sm[i][j];       // one LDS serves 4 rows
            const u64 sp = pk2(sj, sj);
            d0 = fma2(tp0[i], sp, d0);
            d1 = fma2(tp1[i], sp, d1);
        }
        const u64 gA = pk2(gb[j], gb[j + NN]);
        const u64 gB = pk2(gb[j + 2 * NN], gb[j + 3 * NN]);
        const u64 vA = mul2f(mul2f(d0, d0), gA);
        const u64 vB = mul2f(mul2f(d1, d1), gB);
        sumA = add2f(sumA, vA);
        sumB = add2f(sumB, vB);

        float x, y;
        upk2(vA, x, y);
        ob[j] = x;
        ob[j + NN] = y;
        upk2(vB, x, y);
        ob[j + 2 * NN] = x;
        ob[j + 3 * NN] = y;
    }

    // ---- Phase 4: packed warp reductions, then in-place rescale
#pragma unroll
    for (int off = 16; off > 0; off >>= 1) {
        sumA = add2f(sumA, __shfl_xor_sync(0xffffffffu, sumA, off));
        sumB = add2f(sumB, __shfl_xor_sync(0xffffffffu, sumB, off));
    }
    float s0, s1, s2, s3;
    upk2(sumA, s0, s1);
    upk2(sumB, s2, s3);
    const float inv0 = 1.0f / (s0 + 0.001f);
    const float inv1 = 1.0f / (s1 + 0.001f);
    const float inv2 = 1.0f / (s2 + 0.001f);
    const float inv3 = 1.0f / (s3 + 0.001f);

#pragma unroll
    for (int u = 0; u < 16; u++) {
        const int j = lane + (u << 5);
        ob[j]          *= inv0;                 // same-thread RAW, L2-hot
        ob[j + NN]     *= inv1;
        ob[j + 2 * NN] *= inv2;
        ob[j + 3 * NN] *= inv3;
    }
}

// ---------------------------------------------------------------------------
extern "C" void kernel_launch(void* const* d_in, const int* in_sizes, int n_in,
                              void* d_out, int out_size) {
    const float* s    = (const float*)d_in[0];
    const float* Gmat = (const float*)d_in[1];
    const float* Qw   = (const float*)d_in[2];
    const float* Kw   = (const float*)d_in[3];
    float* out = (float*)d_out;

    attn_fused<<<BB * CHUNKS, THREADS>>>(s, Gmat, Qw, Kw, out);
}

// round 8
// speedup vs baseline: 1.5263x; 1.5263x over previous
#include <cuda_runtime.h>

#define BB 256
#define NN 512
#define INF 10
#define HIDF 32
#define R 8                       // rows per block
#define WARPS 8
#define THREADS (WARPS * 32)
#define CHUNKS (NN / R)           // 64

typedef unsigned long long u64;

// ---- packed f32x2 helpers (sm_103a FFMA2 path, PTX-only) -------------------
__device__ __forceinline__ u64 pk2(float lo, float hi) {
    u64 r; asm("mov.b64 %0,{%1,%2};" : "=l"(r) : "f"(lo), "f"(hi)); return r;
}
__device__ __forceinline__ void upk2(u64 v, float& lo, float& hi) {
    asm("mov.b64 {%0,%1},%2;" : "=f"(lo), "=f"(hi) : "l"(v));
}
__device__ __forceinline__ u64 fma2(u64 a, u64 b, u64 c) {
    u64 r; asm("fma.rn.f32x2 %0,%1,%2,%3;" : "=l"(r) : "l"(a), "l"(b), "l"(c)); return r;
}
__device__ __forceinline__ u64 mul2f(u64 a, u64 b) {
    u64 r; asm("mul.rn.f32x2 %0,%1,%2;" : "=l"(r) : "l"(a), "l"(b)); return r;
}
__device__ __forceinline__ u64 add2f(u64 a, u64 b) {
    u64 r; asm("add.rn.f32x2 %0,%1,%2;" : "=l"(r) : "l"(a), "l"(b)); return r;
}

__device__ float g_M[INF * INF];  // M = Q @ K^T  (tiny prolog kernel)

// ---------------------------------------------------------------------------
// Kernel 0: M[a][p] = sum_m Qw[a][m] * Kw[p][m]
// ---------------------------------------------------------------------------
__global__ void compute_M_kernel(const float* __restrict__ Qw,
                                 const float* __restrict__ Kw) {
    int idx = threadIdx.x;
    if (idx < INF * INF) {
        int a = idx / INF, p = idx % INF;
        float acc = 0.0f;
#pragma unroll
        for (int m = 0; m < HIDF; m++)
            acc = fmaf(Qw[a * HIDF + m], Kw[p * HIDF + m], acc);
        g_M[idx] = acc;
    }
}

// ---------------------------------------------------------------------------
// Main kernel. Block = (batch b, 8-row chunk). Lane owns j-pair {j0, j0+1},
// j0 = 64*warp + 2*lane, with s[j0..j0+1][i] packed in 10 u64 registers for
// the whole block (loaded once from L2-hot s). Per row: t broadcast from
// smem, 10 fma2 over packed j, coalesced LDG.64 of G, packed shuffle
// row-reduction, cross-warp partial combine in smem, STG.64 epilogue.
// Normalization is single-pass: v stays in acc[R] registers.
// ---------------------------------------------------------------------------
__global__ __launch_bounds__(THREADS, 3) void attn_main(
    const float* __restrict__ s,
    const float* __restrict__ Gmat,
    float* __restrict__ out) {
    __shared__ float Msh[INF * INF];
    __shared__ float srow_sm[R][INF];
    __shared__ float t_sm[R][INF];
    __shared__ float psum[R][WARPS];
    __shared__ float inv_sm[R];

    const int tid = threadIdx.x;
    const int b = blockIdx.x / CHUNKS;
    const int row0 = (blockIdx.x % CHUNKS) * R;

    // ---- prolog: M -> smem, s rows (for t) -> smem
    if (tid < INF * INF) Msh[tid] = g_M[tid];
    if (tid < R * INF) {
        const int r = tid / INF, i = tid % INF;
        srow_sm[r][i] = s[((size_t)b * NN + row0 + r) * INF + i];
    }

    // ---- lane-private s for its j-pair (L2-hot, no sync needed)
    const int w = tid >> 5, l = tid & 31;
    const int j0 = (w << 6) + (l << 1);
    u64 s2[INF];
    {
        const float* sj = s + ((size_t)b * NN + j0) * INF;
#pragma unroll
        for (int i = 0; i < INF; i++)
            s2[i] = pk2(sj[i], sj[i + INF]);
    }
    __syncthreads();

    // ---- t[r][o] = sum_l srow[r][l] * M[l][o]   (80 threads)
    if (tid < R * INF) {
        const int r = tid / INF, o = tid % INF;
        float acc = 0.0f;
#pragma unroll
        for (int ll = 0; ll < INF; ll++)
            acc = fmaf(srow_sm[r][ll], Msh[ll * INF + o], acc);
        t_sm[r][o] = acc;
    }
    __syncthreads();

    // ---- main: sweep the 8 rows; lane covers its packed j-pair
    const float* gp = Gmat + ((size_t)b * NN + row0) * NN + j0;
    u64 acc[R];

#pragma unroll
    for (int r = 0; r < R; r++) {
        u64 d = pk2(0.0f, 0.0f);
#pragma unroll
        for (int i = 0; i < INF; i++) {
            const float tv = t_sm[r][i];          // warp-uniform broadcast
            d = fma2(s2[i], pk2(tv, tv), d);
        }
        const u64 g = *(const u64*)(gp + (size_t)r * NN);   // LDG.64 coalesced
        const u64 v = mul2f(mul2f(d, d), g);
        acc[r] = v;

        u64 sred = v;                              // packed row-sum reduce
#pragma unroll
        for (int off = 16; off > 0; off >>= 1)
            sred = add2f(sred, __shfl_xor_sync(0xffffffffu, sred, off));
        if (l == 0) {
            float a, bv;
            upk2(sred, a, bv);
            psum[r][w] = a + bv;
        }
    }
    __syncthreads();

    // ---- combine warp partials, compute 1/(sum + 1e-3)
    if (tid < R) {
        float ssum = 0.0f;
#pragma unroll
        for (int ww = 0; ww < WARPS; ww++) ssum += psum[tid][ww];
        inv_sm[tid] = 1.0f / (ssum + 0.001f);
    }
    __syncthreads();

    // ---- normalized stores (STG.64)
    float* op = out + ((size_t)b * NN + row0) * NN + j0;
#pragma unroll
    for (int r = 0; r < R; r++) {
        const float iv = inv_sm[r];
        const u64 o2 = mul2f(acc[r], pk2(iv, iv));
        *(u64*)(op + (size_t)r * NN) = o2;
    }
}

// ---------------------------------------------------------------------------
extern "C" void kernel_launch(void* const* d_in, const int* in_sizes, int n_in,
                              void* d_out, int out_size) {
    const float* s    = (const float*)d_in[0];
    const float* Gmat = (const float*)d_in[1];
    const float* Qw   = (const float*)d_in[2];
    const float* Kw   = (const float*)d_in[3];
    float* out = (float*)d_out;

    compute_M_kernel<<<1, 128>>>(Qw, Kw);
    attn_main<<<BB * CHUNKS, THREADS>>>(s, Gmat, out);
}

// round 9
// speedup vs baseline: 1.7003x; 1.1140x over previous
#include <cuda_runtime.h>

#define BB 256
#define NN 512
#define INF 10
#define HIDF 32
#define R 16                      // rows per block
#define WARPS 8
#define THREADS (WARPS * 32)
#define CHUNKS (NN / R)           // 32

typedef unsigned long long u64;

// ---- packed f32x2 helpers (sm_103a FFMA2 path, PTX-only) -------------------
__device__ __forceinline__ u64 pk2(float lo, float hi) {
    u64 r; asm("mov.b64 %0,{%1,%2};" : "=l"(r) : "f"(lo), "f"(hi)); return r;
}
__device__ __forceinline__ void upk2(u64 v, float& lo, float& hi) {
    asm("mov.b64 {%0,%1},%2;" : "=f"(lo), "=f"(hi) : "l"(v));
}
__device__ __forceinline__ u64 fma2(u64 a, u64 b, u64 c) {
    u64 r; asm("fma.rn.f32x2 %0,%1,%2,%3;" : "=l"(r) : "l"(a), "l"(b), "l"(c)); return r;
}
__device__ __forceinline__ u64 mul2f(u64 a, u64 b) {
    u64 r; asm("mul.rn.f32x2 %0,%1,%2;" : "=l"(r) : "l"(a), "l"(b)); return r;
}
__device__ __forceinline__ u64 add2f(u64 a, u64 b) {
    u64 r; asm("add.rn.f32x2 %0,%1,%2;" : "=l"(r) : "l"(a), "l"(b)); return r;
}

__device__ float g_M[INF * INF];  // M = Q @ K^T

// ---------------------------------------------------------------------------
__global__ void compute_M_kernel(const float* __restrict__ Qw,
                                 const float* __restrict__ Kw) {
    int idx = threadIdx.x;
    if (idx < INF * INF) {
        int a = idx / INF, p = idx % INF;
        float acc = 0.0f;
#pragma unroll
        for (int m = 0; m < HIDF; m++)
            acc = fmaf(Qw[a * HIDF + m], Kw[p * HIDF + m], acc);
        g_M[idx] = acc;
    }
}

// ---------------------------------------------------------------------------
// Block = (batch b, 16-row chunk). Lane owns j-pair {j0, j0+1}.
//   Stage 1: s[b] (20 KB) -> smem via fully coalesced loads; M -> smem.
//   Stage 2: lane builds s2[10] (packed j-pair) via 5 aligned LDS.128;
//            threads 0..159 compute t = s.M for the 16 rows.
//   Stage 3: sweep rows; per row: warp-uniform t broadcast, 10 fma2 with
//            split accumulators, coalesced LDG.64 of G, v kept in acc[R],
//            scalar 5-shuffle row-sum, partials combined in smem.
//   Stage 4: single-pass normalized STG.64.
// ---------------------------------------------------------------------------
__global__ __launch_bounds__(THREADS, 3) void attn_main(
    const float* __restrict__ s,
    const float* __restrict__ Gmat,
    float* __restrict__ out) {
    __shared__ float s_sm[NN * INF];     // s[b], row-major (20 KB)
    __shared__ float Msh[INF * INF];
    __shared__ float t_sm[R][INF];
    __shared__ float psum[R][WARPS];
    __shared__ float inv_sm[R];

    const int tid = threadIdx.x;
    const int b = blockIdx.x / CHUNKS;
    const int row0 = (blockIdx.x % CHUNKS) * R;

    // ---- Stage 1: coalesced staging of s[b] + M
    {
        const float* sb = s + (size_t)b * NN * INF;
#pragma unroll
        for (int k = 0; k < (NN * INF) / THREADS; k++)
            s_sm[tid + k * THREADS] = sb[tid + k * THREADS];
    }
    if (tid < INF * INF) Msh[tid] = g_M[tid];
    __syncthreads();

    // ---- Stage 2a: lane-private packed s for its j-pair (5 aligned LDS.128)
    const int w = tid >> 5, l = tid & 31;
    const int j0 = (w << 6) + (l << 1);
    u64 s2[INF];
    {
        const float4* p4 = (const float4*)(s_sm + j0 * INF);  // j0*40 B, 16-aligned
        float4 f0 = p4[0], f1 = p4[1], f2 = p4[2], f3 = p4[3], f4v = p4[4];
        // row j0:   f0.x f0.y f0.z f0.w f1.x f1.y f1.z f1.w f2.x f2.y
        // row j0+1: f2.z f2.w f3.x f3.y f3.z f3.w f4.x f4.y f4.z f4.w
        s2[0] = pk2(f0.x, f2.z);  s2[1] = pk2(f0.y, f2.w);
        s2[2] = pk2(f0.z, f3.x);  s2[3] = pk2(f0.w, f3.y);
        s2[4] = pk2(f1.x, f3.z);  s2[5] = pk2(f1.y, f3.w);
        s2[6] = pk2(f1.z, f4v.x); s2[7] = pk2(f1.w, f4v.y);
        s2[8] = pk2(f2.x, f4v.z); s2[9] = pk2(f2.y, f4v.w);
    }

    // ---- Stage 2b: t[r][o] = sum_l s[row0+r][l] * M[l][o]  (160 threads)
    if (tid < R * INF) {
        const int r = tid / INF, o = tid % INF;
        const float* srow = s_sm + (row0 + r) * INF;
        float acc = 0.0f;
#pragma unroll
        for (int ll = 0; ll < INF; ll++)
            acc = fmaf(srow[ll], Msh[ll * INF + o], acc);
        t_sm[r][o] = acc;
    }
    __syncthreads();

    // ---- Stage 3: main sweep over the 16 rows
    const float* gp = Gmat + ((size_t)b * NN + row0) * NN + j0;
    u64 acc[R];

#pragma unroll
    for (int r = 0; r < R; r++) {
        float tv[INF];
#pragma unroll
        for (int i = 0; i < INF; i++) tv[i] = t_sm[r][i];   // broadcast LDS

        u64 da = pk2(0.0f, 0.0f);
        u64 db = pk2(0.0f, 0.0f);
#pragma unroll
        for (int i = 0; i < INF; i += 2) {
            da = fma2(s2[i],     pk2(tv[i],     tv[i]),     da);
            db = fma2(s2[i + 1], pk2(tv[i + 1], tv[i + 1]), db);
        }
        const u64 d = add2f(da, db);
        const u64 g = *(const u64*)(gp + (size_t)r * NN);   // LDG.64 coalesced
        const u64 v = mul2f(mul2f(d, d), g);
        acc[r] = v;

        float lo, hi;
        upk2(v, lo, hi);
        float sv = lo + hi;                                  // scalar reduce
#pragma unroll
        for (int off = 16; off > 0; off >>= 1)
            sv += __shfl_xor_sync(0xffffffffu, sv, off);
        if (l == 0) psum[r][w] = sv;
    }
    __syncthreads();

    // ---- combine warp partials
    if (tid < R) {
        float ssum = 0.0f;
#pragma unroll
        for (int ww = 0; ww < WARPS; ww++) ssum += psum[tid][ww];
        inv_sm[tid] = 1.0f / (ssum + 0.001f);
    }
    __syncthreads();

    // ---- Stage 4: normalized stores (STG.64)
    float* op = out + ((size_t)b * NN + row0) * NN + j0;
#pragma unroll
    for (int r = 0; r < R; r++) {
        const float iv = inv_sm[r];
        *(u64*)(op + (size_t)r * NN) = mul2f(acc[r], pk2(iv, iv));
    }
}

// ---------------------------------------------------------------------------
extern "C" void kernel_launch(void* const* d_in, const int* in_sizes, int n_in,
                              void* d_out, int out_size) {
    const float* s    = (const float*)d_in[0];
    const float* Gmat = (const float*)d_in[1];
    const float* Qw   = (const float*)d_in[2];
    const float* Kw   = (const float*)d_in[3];
    float* out = (float*)d_out;

    compute_M_kernel<<<1, 128>>>(Qw, Kw);
    attn_main<<<BB * CHUNKS, THREADS>>>(s, Gmat, out);
}